// round 16
// baseline (speedup 1.0000x reference)
#include <cuda_runtime.h>
#include <cuda_bf16.h>
#include <math_constants.h>

#define P_PATCHES 1024
#define MAX_BS 16

// Per-patch (start, end) token range; segment = [x, y).
__device__ int2 g_bnd[MAX_BS * P_PATCHES];

// Scatter bounds: token t fills every boundary falling in the gap
// (pid[t-1], pid[t]]. Each field written exactly once; O(1) expected work.
__global__ void __launch_bounds__(256)
bounds_scatter(const int* __restrict__ pids, int seq)
{
    const int b = blockIdx.y;
    const int t = blockIdx.x * blockDim.x + threadIdx.x;
    if (t >= seq) return;
    const int* pid_b = pids + (long)b * seq;
    const int cur  = pid_b[t];
    const int prev = (t == 0) ? -1 : pid_b[t - 1];
    int2* bnd = g_bnd + b * P_PATCHES;

    for (int p = prev + 1; p <= cur; ++p) bnd[p].x = t;       // starts
    for (int q = max(prev, 0); q < cur; ++q) bnd[q].y = t;    // ends

    if (t == seq - 1) {                                       // trailing patches
        for (int p = cur + 1; p < P_PATCHES; ++p) bnd[p].x = seq;
        for (int q = cur; q < P_PATCHES; ++q) bnd[q].y = seq;
    }
}

// Plain running top-2: 3 FMNMX per scalar. Every real token fed EXACTLY once
// (plain top-2 is not idempotent — no clamped re-loads). Differs from the
// reference only on bitwise ties at a cell max; measured deterministic
// rel_err 2.5e-4 on the fixed dataset (threshold 1e-3).
__device__ __forceinline__ void upd(float v, float& m1, float& m2) {
    m2 = fmaxf(m2, fminf(v, m1));
    m1 = fmaxf(m1, v);
}

__device__ __forceinline__ void upd4(const float4& v, float4& m1, float4& m2) {
    upd(v.x, m1.x, m2.x);
    upd(v.y, m1.y, m2.y);
    upd(v.z, m1.z, m2.z);
    upd(v.w, m1.w, m2.w);
}

// Process exactly N tokens: N independent loads batched up front (one memory
// round), then N updates. N is warp-uniform. Max N=5 keeps the register
// high-water at ~20 buffer regs (occupancy!).
template <int E, int N>
__device__ __forceinline__ void procN(const float* __restrict__ hb,
                                      float4& m1x, float4& m2x)
{
    float4 v[N];
#pragma unroll
    for (int i = 0; i < N; ++i) v[i] = *(const float4*)(hb + i * E);
#pragma unroll
    for (int i = 0; i < N; ++i) upd4(v[i], m1x, m2x);
}

template <int E>
__global__ void __launch_bounds__(128)
topk_mean_kernel(const float* __restrict__ h,
                 float* __restrict__ out,
                 int seq)
{
    const int p = blockIdx.x;
    const int b = blockIdx.y;

    const int2 se = g_bnd[b * P_PATCHES + p];   // one LDG.64, L2-resident
    const int start = se.x;
    const int count = se.y - se.x;

    float4* outv = (float4*)(out + (((long)b * P_PATCHES + p) * E) + threadIdx.x * 4);

    if (count == 0) { *outv = make_float4(0.f, 0.f, 0.f, 0.f); return; }

    const float* hb = h + ((long)b * seq + start) * E + threadIdx.x * 4;

    // count==1: mean of top-2 over one token is the token itself.
    if (count == 1) { *outv = *(const float4*)hb; return; }

    float4 m1 = make_float4(-CUDART_INF_F, -CUDART_INF_F, -CUDART_INF_F, -CUDART_INF_F);
    float4 m2 = m1;

    // Warp-uniform dispatch. Counts 2-5 (~66%): ONE batched memory round with
    // a <=20-reg buffer. Counts 6-8 (~19%): two batched rounds (4 + N-4) —
    // trades a second round on the tail for kernel-wide occupancy.
    switch (count) {
        case 2: procN<E, 2>(hb, m1, m2); break;
        case 3: procN<E, 3>(hb, m1, m2); break;
        case 4: procN<E, 4>(hb, m1, m2); break;
        case 5: procN<E, 5>(hb, m1, m2); break;
        case 6: procN<E, 4>(hb, m1, m2); procN<E, 2>(hb + 4 * E, m1, m2); break;
        case 7: procN<E, 4>(hb, m1, m2); procN<E, 3>(hb + 4 * E, m1, m2); break;
        case 8: procN<E, 4>(hb, m1, m2); procN<E, 4>(hb + 4 * E, m1, m2); break;
        default: {
            // Rare (count > 8): 4-wide groups + exact uniform remainder.
            const int r  = count & 3;
            const int n4 = count - r;
            const int end4 = n4 * E;
            int off = 0;
            while (off < end4) {
                procN<E, 4>(hb + off, m1, m2);
                off += 4 * E;
            }
            if (r == 1)      procN<E, 1>(hb + end4, m1, m2);
            else if (r == 2) procN<E, 2>(hb + end4, m1, m2);
            else if (r == 3) procN<E, 3>(hb + end4, m1, m2);
            break;
        }
    }

    // count>=2 exact-count plain top-2: m2 is always a real token value.
    *outv = make_float4((m1.x + m2.x) * 0.5f, (m1.y + m2.y) * 0.5f,
                        (m1.z + m2.z) * 0.5f, (m1.w + m2.w) * 0.5f);
}

extern "C" void kernel_launch(void* const* d_in, const int* in_sizes, int n_in,
                              void* d_out, int out_size)
{
    const float* h    = (const float*)d_in[0];
    const int*   pids = (const int*)d_in[1];
    float*       out  = (float*)d_out;

    const int total_tok = in_sizes[1];           // bs * seq
    const int E  = in_sizes[0] / total_tok;      // 512
    const int bs = out_size / (P_PATCHES * E);   // 8
    const int seq = total_tok / bs;              // 4096

    {
        dim3 grid((seq + 255) / 256, bs);
        bounds_scatter<<<grid, 256>>>(pids, seq);
    }

    dim3 grid(P_PATCHES, bs);                    // CTA per patch: 8192 CTAs
    if (E == 512) {
        topk_mean_kernel<512><<<grid, 128>>>(h, out, seq);
    } else if (E == 256) {
        topk_mean_kernel<256><<<grid, 64>>>(h, out, seq);
    } else if (E == 1024) {
        topk_mean_kernel<1024><<<grid, 256>>>(h, out, seq);
    }
}

// round 17
// speedup vs baseline: 1.3800x; 1.3800x over previous
#include <cuda_runtime.h>
#include <cuda_bf16.h>
#include <math_constants.h>

#define P_PATCHES 1024
#define MAX_BS 16

// Per-patch (start, end) token range; segment = [x, y).
__device__ int2 g_bnd[MAX_BS * P_PATCHES];

// Scatter bounds: token t fills every boundary falling in the gap
// (pid[t-1], pid[t]]. Each field written exactly once; O(1) expected work.
__global__ void __launch_bounds__(256)
bounds_scatter(const int* __restrict__ pids, int seq)
{
    const int b = blockIdx.y;
    const int t = blockIdx.x * blockDim.x + threadIdx.x;
    if (t >= seq) return;
    const int* pid_b = pids + (long)b * seq;
    const int cur  = pid_b[t];
    const int prev = (t == 0) ? -1 : pid_b[t - 1];
    int2* bnd = g_bnd + b * P_PATCHES;

    for (int p = prev + 1; p <= cur; ++p) bnd[p].x = t;       // starts
    for (int q = max(prev, 0); q < cur; ++q) bnd[q].y = t;    // ends

    if (t == seq - 1) {                                       // trailing patches
        for (int p = cur + 1; p < P_PATCHES; ++p) bnd[p].x = seq;
        for (int q = cur; q < P_PATCHES; ++q) bnd[q].y = seq;
    }
}

// Plain running top-2: 3 FMNMX per scalar. Every real token fed EXACTLY once
// (plain top-2 is not idempotent — no clamped re-loads). Differs from the
// reference only on bitwise ties at a cell max; measured deterministic
// rel_err 2.5e-4 on the fixed dataset (threshold 1e-3).
__device__ __forceinline__ void upd(float v, float& m1, float& m2) {
    m2 = fmaxf(m2, fminf(v, m1));
    m1 = fmaxf(m1, v);
}

__device__ __forceinline__ void upd4(const float4& v, float4& m1, float4& m2) {
    upd(v.x, m1.x, m2.x);
    upd(v.y, m1.y, m2.y);
    upd(v.z, m1.z, m2.z);
    upd(v.w, m1.w, m2.w);
}

// Process exactly N tokens: N independent loads batched up front (one memory
// round), then N updates. N is warp-uniform.
template <int E, int N>
__device__ __forceinline__ void procN(const float* __restrict__ hb,
                                      float4& m1x, float4& m2x)
{
    float4 v[N];
#pragma unroll
    for (int i = 0; i < N; ++i) v[i] = *(const float4*)(hb + i * E);
#pragma unroll
    for (int i = 0; i < N; ++i) upd4(v[i], m1x, m2x);
}

template <int E>
__global__ void __launch_bounds__(128)
topk_mean_kernel(const float* __restrict__ h,
                 float* __restrict__ out,
                 int seq)
{
    const int p = blockIdx.x;
    const int b = blockIdx.y;

    const int2 se = __ldg(&g_bnd[b * P_PATCHES + p]);   // one LDG.64
    const int start = se.x;
    const int count = se.y - se.x;

    float4* outv = (float4*)(out + (((long)b * P_PATCHES + p) * E) + threadIdx.x * 4);

    if (count == 0) { *outv = make_float4(0.f, 0.f, 0.f, 0.f); return; }

    const float* hb = h + ((long)b * seq + start) * E + threadIdx.x * 4;

    // count==1: mean of top-2 over one token is the token itself.
    if (count == 1) { *outv = *(const float4*)hb; return; }

    // count==2: mean of top-2 of two values = their mean. 2 ops/scalar.
    if (count == 2) {
        float4 v0 = *(const float4*)(hb);
        float4 v1 = *(const float4*)(hb + E);
        *outv = make_float4((v0.x + v1.x) * 0.5f, (v0.y + v1.y) * 0.5f,
                            (v0.z + v1.z) * 0.5f, (v0.w + v1.w) * 0.5f);
        return;
    }

    // count==3: mean of top-2 of three = (sum - min) / 2. 5 ops/scalar.
    if (count == 3) {
        float4 v0 = *(const float4*)(hb);
        float4 v1 = *(const float4*)(hb + E);
        float4 v2 = *(const float4*)(hb + 2 * E);
        *outv = make_float4(
            (v0.x + v1.x + v2.x - fminf(v0.x, fminf(v1.x, v2.x))) * 0.5f,
            (v0.y + v1.y + v2.y - fminf(v0.y, fminf(v1.y, v2.y))) * 0.5f,
            (v0.z + v1.z + v2.z - fminf(v0.z, fminf(v1.z, v2.z))) * 0.5f,
            (v0.w + v1.w + v2.w - fminf(v0.w, fminf(v1.w, v2.w))) * 0.5f);
        return;
    }

    float4 m1 = make_float4(-CUDART_INF_F, -CUDART_INF_F, -CUDART_INF_F, -CUDART_INF_F);
    float4 m2 = m1;

    // Warp-uniform dispatch: one batched memory round for count <= 8 (>98%).
    switch (count) {
        case 4: procN<E, 4>(hb, m1, m2); break;
        case 5: procN<E, 5>(hb, m1, m2); break;
        case 6: procN<E, 6>(hb, m1, m2); break;
        case 7: procN<E, 7>(hb, m1, m2); break;
        case 8: procN<E, 8>(hb, m1, m2); break;
        default: {
            // Rare (count > 8): 4-wide groups + exact uniform remainder.
            const int r  = count & 3;
            const int n4 = count - r;
            const int end4 = n4 * E;
            int off = 0;
            while (off < end4) {
                procN<E, 4>(hb + off, m1, m2);
                off += 4 * E;
            }
            if (r == 1)      procN<E, 1>(hb + end4, m1, m2);
            else if (r == 2) procN<E, 2>(hb + end4, m1, m2);
            else if (r == 3) procN<E, 3>(hb + end4, m1, m2);
            break;
        }
    }

    // count>=2 exact-count plain top-2: m2 is always a real token value.
    *outv = make_float4((m1.x + m2.x) * 0.5f, (m1.y + m2.y) * 0.5f,
                        (m1.z + m2.z) * 0.5f, (m1.w + m2.w) * 0.5f);
}

extern "C" void kernel_launch(void* const* d_in, const int* in_sizes, int n_in,
                              void* d_out, int out_size)
{
    const float* h    = (const float*)d_in[0];
    const int*   pids = (const int*)d_in[1];
    float*       out  = (float*)d_out;

    const int total_tok = in_sizes[1];           // bs * seq
    const int E  = in_sizes[0] / total_tok;      // 512
    const int bs = out_size / (P_PATCHES * E);   // 8
    const int seq = total_tok / bs;              // 4096

    {
        dim3 grid((seq + 255) / 256, bs);
        bounds_scatter<<<grid, 256>>>(pids, seq);
    }

    dim3 grid(P_PATCHES, bs);                    // CTA per patch: 8192 CTAs
    if (E == 512) {
        topk_mean_kernel<512><<<grid, 128>>>(h, out, seq);
    } else if (E == 256) {
        topk_mean_kernel<256><<<grid, 64>>>(h, out, seq);
    } else if (E == 1024) {
        topk_mean_kernel<1024><<<grid, 256>>>(h, out, seq);
    }
}